// round 3
// baseline (speedup 1.0000x reference)
#include <cuda_runtime.h>
#include <cuda_fp16.h>

#define B_ 256
#define P_ 2048
#define C_ 10
#define O_ 16
#define I_ 8
#define PT 2      // p-tile for u_hat kernel
#define PCH 32    // p-chunk per routing block
#define RB 4      // p's per barrier round in routing

// u_hat as half2 pairs (o even, o odd), layout [p][c][b][o2]:
// lane=b reads/writes 32 contiguous bytes (2x LDG.128 / STG.128).
__device__ __align__(16) __half2 g_uhat[(size_t)P_ * C_ * B_ * (O_ / 2)];
__device__ __align__(16) float g_s[B_ * C_ * O_];      // zero-init; invariant: 0 at entry
__device__ __align__(16) float g_vsum[B_ * C_ * O_];

typedef unsigned long long ull;

__device__ __forceinline__ ull ffma2(ull a, ull b, ull c) {
    ull d;
    asm("fma.rn.f32x2 %0, %1, %2, %3;" : "=l"(d) : "l"(a), "l"(b), "l"(c));
    return d;
}
__device__ __forceinline__ ull pack2(float x, float y) {
    ull r;
    asm("mov.b64 %0, {%1, %2};" : "=l"(r) : "f"(x), "f"(y));
    return r;
}
__device__ __forceinline__ float2 unpack2(ull a) {
    float2 f;
    asm("mov.b64 {%0, %1}, %2;" : "=f"(f.x), "=f"(f.y) : "l"(a));
    return f;
}
__device__ __forceinline__ float rcp_fast(float x) {
    float r;
    asm("rcp.approx.f32 %0, %1;" : "=f"(r) : "f"(x));
    return r;
}

// ---------------------------------------------------------------------------
// K1: u_hat[b,p,c,o] = sum_i W[p,c,o,i]*u[b,p,i], stored fp16.
// 128 threads, each handles TWO b's (t, t+128) so every broadcast W LDS
// feeds 2x the FFMA2 work. W tile transposed in smem to [pc][i][o] so
// o-adjacent pairs share the u[i] multiplier -> packed fma.rn.f32x2.
// ---------------------------------------------------------------------------
__global__ void __launch_bounds__(128) k_uhat(const float* __restrict__ u,
                                              const float* __restrict__ W) {
    __shared__ float Ws[PT * C_ * I_ * O_];  // [pc][i][o], 2560 floats = 10KB

    const int t = threadIdx.x;           // b0 = t, b1 = t + 128
    const int p0 = blockIdx.x * PT;

    // Cooperative load + transpose of the W tile (640 float4s / 128 thr).
    {
        const float4* Wg = (const float4*)(W + (size_t)p0 * C_ * O_ * I_);
#pragma unroll
        for (int k = 0; k < (PT * C_ * O_ * I_) / 4 / 128; k++) {
            float4 w4 = Wg[t + k * 128];
            int L = (t + k * 128) * 4;       // element index in [pc][o][i]
            int i = L & 7;                    // 0 or 4
            int o = (L >> 3) & 15;
            int pc = L >> 7;
            float* dst = Ws + pc * (I_ * O_) + o;
            dst[(i + 0) * O_] = w4.x;
            dst[(i + 1) * O_] = w4.y;
            dst[(i + 2) * O_] = w4.z;
            dst[(i + 3) * O_] = w4.w;
        }
    }

    // u for both b's, both p's.
    float ur[2][PT][I_];
#pragma unroll
    for (int bb = 0; bb < 2; bb++) {
        const int b = t + bb * 128;
        const float4* ug = (const float4*)(u + ((size_t)b * P_ + p0) * I_);
#pragma unroll
        for (int p = 0; p < PT; p++) {
            float4 a = ug[p * 2 + 0];
            float4 d = ug[p * 2 + 1];
            ur[bb][p][0] = a.x; ur[bb][p][1] = a.y; ur[bb][p][2] = a.z; ur[bb][p][3] = a.w;
            ur[bb][p][4] = d.x; ur[bb][p][5] = d.y; ur[bb][p][6] = d.z; ur[bb][p][7] = d.w;
        }
    }
    __syncthreads();

#pragma unroll 1
    for (int p = 0; p < PT; p++) {
        ull uu[2][I_];
#pragma unroll
        for (int bb = 0; bb < 2; bb++)
#pragma unroll
            for (int i = 0; i < I_; i++)
                uu[bb][i] = pack2(ur[bb][p][i], ur[bb][p][i]);

#pragma unroll 1
        for (int c = 0; c < C_; c++) {
            const ulonglong2* w2 = (const ulonglong2*)(Ws + (p * C_ + c) * I_ * O_);
            ull a0[8], a1[8];
#pragma unroll
            for (int k = 0; k < 8; k++) { a0[k] = 0ULL; a1[k] = 0ULL; }
#pragma unroll
            for (int i = 0; i < I_; i++) {
                ulonglong2 q0 = w2[i * 4 + 0];
                ulonglong2 q1 = w2[i * 4 + 1];
                ulonglong2 q2 = w2[i * 4 + 2];
                ulonglong2 q3 = w2[i * 4 + 3];
                a0[0] = ffma2(q0.x, uu[0][i], a0[0]);  a1[0] = ffma2(q0.x, uu[1][i], a1[0]);
                a0[1] = ffma2(q0.y, uu[0][i], a0[1]);  a1[1] = ffma2(q0.y, uu[1][i], a1[1]);
                a0[2] = ffma2(q1.x, uu[0][i], a0[2]);  a1[2] = ffma2(q1.x, uu[1][i], a1[2]);
                a0[3] = ffma2(q1.y, uu[0][i], a0[3]);  a1[3] = ffma2(q1.y, uu[1][i], a1[3]);
                a0[4] = ffma2(q2.x, uu[0][i], a0[4]);  a1[4] = ffma2(q2.x, uu[1][i], a1[4]);
                a0[5] = ffma2(q2.y, uu[0][i], a0[5]);  a1[5] = ffma2(q2.y, uu[1][i], a1[5]);
                a0[6] = ffma2(q3.x, uu[0][i], a0[6]);  a1[6] = ffma2(q3.x, uu[1][i], a1[6]);
                a0[7] = ffma2(q3.y, uu[0][i], a0[7]);  a1[7] = ffma2(q3.y, uu[1][i], a1[7]);
            }
            __half2* base = g_uhat + (((size_t)(p0 + p) * C_ + c) * B_) * 8;
            {
                union { __half2 h[8]; uint4 q[2]; } ou;
#pragma unroll
                for (int k = 0; k < 8; k++) {
                    float2 f = unpack2(a0[k]);
                    ou.h[k] = __floats2half2_rn(f.x, f.y);
                }
                uint4* dst = (uint4*)(base + (size_t)t * 8);
                dst[0] = ou.q[0];
                dst[1] = ou.q[1];
            }
            {
                union { __half2 h[8]; uint4 q[2]; } ou;
#pragma unroll
                for (int k = 0; k < 8; k++) {
                    float2 f = unpack2(a1[k]);
                    ou.h[k] = __floats2half2_rn(f.x, f.y);
                }
                uint4* dst = (uint4*)(base + (size_t)(t + 128) * 8);
                dst[0] = ou.q[0];
                dst[1] = ou.q[1];
            }
        }
    }
}

// ---------------------------------------------------------------------------
// Routing pass. warp = capsule c (10 warps), lane = b within a 32-b tile.
// Rounds of RB=4 p's held IN REGISTERS across the softmax exchange:
// (1) batched loads + HFMA2 logits + exp -> smem, (2) barrier, warps 0..RB-1
// compute rcp(Z), (3) barrier, accumulate with packed f32x2 FMA from regs.
// UNIFORM=true => iter 1 (softmax(0)=0.1), pure stream, no barriers.
// ---------------------------------------------------------------------------
template <bool UNIFORM>
__global__ void __launch_bounds__(320, 3) k_route() {
    const int c = threadIdx.x >> 5;
    const int lane = threadIdx.x & 31;
    const int b = blockIdx.y * 32 + lane;
    const int p0 = blockIdx.x * PCH;

    __shared__ float es[RB][C_][32];
    __shared__ float rz[RB][32];

    __half2 vsh[8];
    if (!UNIFORM) {
        const float4* vp = (const float4*)(g_vsum + (b * C_ + c) * O_);
#pragma unroll
        for (int k = 0; k < 4; k++) {
            float4 v4 = vp[k];
            vsh[2 * k + 0] = __floats2half2_rn(v4.x, v4.y);
            vsh[2 * k + 1] = __floats2half2_rn(v4.z, v4.w);
        }
    }

    ull acc[8];
#pragma unroll
    for (int k = 0; k < 8; k++) acc[k] = 0ULL;

#pragma unroll 1
    for (int r = 0; r < PCH / RB; r++) {
        const int pb = p0 + r * RB;

        if (UNIFORM) {
            const ull cw2 = pack2(0.1f, 0.1f);
#pragma unroll
            for (int j = 0; j < RB; j++) {
                const uint4* src =
                    (const uint4*)(g_uhat + (((size_t)(pb + j) * C_ + c) * B_ + b) * 8);
                union { uint4 q[2]; __half2 h[8]; } uu;
                uu.q[0] = src[0];
                uu.q[1] = src[1];
#pragma unroll
                for (int k = 0; k < 8; k++) {
                    float2 f = __half22float2(uu.h[k]);
                    acc[k] = ffma2(cw2, pack2(f.x, f.y), acc[k]);
                }
            }
        } else {
            union { uint4 q[2]; __half2 h[8]; } uu[RB];
            float e[RB];
            // Phase 1: batched loads, logits, exp.
#pragma unroll
            for (int j = 0; j < RB; j++) {
                const uint4* src =
                    (const uint4*)(g_uhat + (((size_t)(pb + j) * C_ + c) * B_ + b) * 8);
                uu[j].q[0] = src[0];
                uu[j].q[1] = src[1];
            }
#pragma unroll
            for (int j = 0; j < RB; j++) {
                __half2 lg = __floats2half2_rn(0.f, 0.f);
#pragma unroll
                for (int k = 0; k < 8; k++) lg = __hfma2(uu[j].h[k], vsh[k], lg);
                float l = __low2float(lg) + __high2float(lg);
                e[j] = __expf(l);   // |logit| small: no max-subtraction needed
                es[j][c][lane] = e[j];
            }
            __syncthreads();
            // Phase 2: one warp per p computes 1/Z.
            if (c < RB) {
                float Z = 0.f;
#pragma unroll
                for (int cc = 0; cc < C_; cc++) Z += es[c][cc][lane];
                rz[c][lane] = rcp_fast(Z);
            }
            __syncthreads();
            // Phase 3: weighted accumulate from registers.
#pragma unroll
            for (int j = 0; j < RB; j++) {
                float cw = e[j] * rz[j][lane];
                ull cw2 = pack2(cw, cw);
#pragma unroll
                for (int k = 0; k < 8; k++) {
                    float2 f = __half22float2(uu[j].h[k]);
                    acc[k] = ffma2(cw2, pack2(f.x, f.y), acc[k]);
                }
            }
            __syncthreads();   // protect es/rz for next round
        }
    }

    float* sp = g_s + (b * C_ + c) * O_;
#pragma unroll
    for (int k = 0; k < 8; k++) {
        float2 f = unpack2(acc[k]);
        atomicAdd(sp + 2 * k + 0, f.x);
        atomicAdd(sp + 2 * k + 1, f.y);
    }
}

// ---------------------------------------------------------------------------
// Squash. MODE 0: vsum=v, s=0.  MODE 1: vsum+=v, s=0.  MODE 2: out=v, s=0.
// ---------------------------------------------------------------------------
template <int MODE>
__global__ void __launch_bounds__(640) k_squash(float* __restrict__ out) {
    const int idx = blockIdx.x * 640 + threadIdx.x;

    float sv = g_s[idx];
    float n2 = sv * sv;
#pragma unroll
    for (int d = 1; d < 16; d <<= 1) n2 += __shfl_xor_sync(0xffffffffu, n2, d);

    float scale = (n2 / (1.f + n2)) * rsqrtf(n2 + 1e-9f);
    float v = sv * scale;

    g_s[idx] = 0.f;
    if (MODE == 0) {
        g_vsum[idx] = v;
    } else if (MODE == 1) {
        g_vsum[idx] += v;
    } else {
        out[idx] = v;
    }
}

// ---------------------------------------------------------------------------
extern "C" void kernel_launch(void* const* d_in, const int* in_sizes, int n_in,
                              void* d_out, int out_size) {
    const float* u = (const float*)d_in[0];
    const float* W = (const float*)d_in[1];
    if (n_in >= 2 && in_sizes[0] == P_ * C_ * O_ * I_ && in_sizes[1] == B_ * P_ * I_) {
        const float* tmp = u; u = W; W = tmp;
    }
    float* out = (float*)d_out;

    dim3 rg(P_ / PCH, B_ / 32);  // (64, 8) = 512 blocks

    k_uhat<<<P_ / PT, 128>>>(u, W);                     // 1024 blocks

    k_route<true><<<rg, 320>>>();                       // iter 1 (uniform)
    k_squash<0><<<(B_ * C_ * O_) / 640, 640>>>(out);    // v1 -> vsum, s=0

    k_route<false><<<rg, 320>>>();                      // iter 2
    k_squash<1><<<(B_ * C_ * O_) / 640, 640>>>(out);    // vsum += v2, s=0

    k_route<false><<<rg, 320>>>();                      // iter 3
    k_squash<2><<<(B_ * C_ * O_) / 640, 640>>>(out);    // out = v3, s=0
}

// round 4
// speedup vs baseline: 1.5314x; 1.5314x over previous
#include <cuda_runtime.h>
#include <cuda_fp16.h>

#define B_ 256
#define P_ 2048
#define C_ 10
#define O_ 16
#define I_ 8
#define PT 2                 // p's per u_hat block
#define PCH 32               // p's per routing block
#define NCHUNK (P_ / PCH)    // 64 routing p-chunks
#define SSZ (B_ * C_ * O_)   // 40960

// u_hat fp16, layout [p][b][c][o2]: one (b,p) record = 320B contiguous.
__device__ __align__(16) __half2 g_uhat[(size_t)P_ * B_ * C_ * (O_ / 2)];
// Per-p-chunk partial s sums (plain stores, no atomics): [chunk][b][c][o].
__device__ __align__(16) float g_part[NCHUNK * SSZ];
__device__ __align__(16) float g_vsum[SSZ];

typedef unsigned long long ull;

__device__ __forceinline__ ull ffma2(ull a, ull b, ull c) {
    ull d;
    asm("fma.rn.f32x2 %0, %1, %2, %3;" : "=l"(d) : "l"(a), "l"(b), "l"(c));
    return d;
}
__device__ __forceinline__ ull pack2(float x, float y) {
    ull r;
    asm("mov.b64 %0, {%1, %2};" : "=l"(r) : "f"(x), "f"(y));
    return r;
}
__device__ __forceinline__ float2 unpack2(ull a) {
    float2 f;
    asm("mov.b64 {%0, %1}, %2;" : "=f"(f.x), "=f"(f.y) : "l"(a));
    return f;
}
__device__ __forceinline__ float rcp_fast(float x) {
    float r;
    asm("rcp.approx.f32 %0, %1;" : "=f"(r) : "f"(x));
    return r;
}

// ---------------------------------------------------------------------------
// K1: u_hat[p][b][c][o] = sum_i W[p,c,o,i]*u[b,p,i], fp16 out.
// thread = b; W tile transposed in smem to [pc][i][o] for packed fma.rn.f32x2.
// Stores: per (p,c) a 32B chunk at record + c*32 (full-sector writes).
// ---------------------------------------------------------------------------
__global__ void __launch_bounds__(256) k_uhat(const float* __restrict__ u,
                                              const float* __restrict__ W) {
    __shared__ float Ws[PT * C_ * I_ * O_];  // 2560 floats = 10KB

    const int t = threadIdx.x;           // = b
    const int p0 = blockIdx.x * PT;

    // Cooperative load + transpose of the W tile (640 float4s).
    {
        const float4* Wg = (const float4*)(W + (size_t)p0 * C_ * O_ * I_);
#pragma unroll
        for (int k = 0; k < 3; k++) {
            int idx = t + k * 256;
            if (idx < (PT * C_ * O_ * I_) / 4) {
                float4 w4 = Wg[idx];
                int L = idx * 4;            // element index in [pc][o][i]
                int i = L & 7;              // 0 or 4
                int o = (L >> 3) & 15;
                int pc = L >> 7;
                float* dst = Ws + pc * (I_ * O_) + o;
                dst[(i + 0) * O_] = w4.x;
                dst[(i + 1) * O_] = w4.y;
                dst[(i + 2) * O_] = w4.z;
                dst[(i + 3) * O_] = w4.w;
            }
        }
    }

    // u[b, p0..p0+PT-1, :] into registers.
    float ur[PT][I_];
    {
        const float4* ug = (const float4*)(u + ((size_t)t * P_ + p0) * I_);
#pragma unroll
        for (int p = 0; p < PT; p++) {
            float4 a = ug[p * 2 + 0];
            float4 d = ug[p * 2 + 1];
            ur[p][0] = a.x; ur[p][1] = a.y; ur[p][2] = a.z; ur[p][3] = a.w;
            ur[p][4] = d.x; ur[p][5] = d.y; ur[p][6] = d.z; ur[p][7] = d.w;
        }
    }
    __syncthreads();

#pragma unroll 1
    for (int p = 0; p < PT; p++) {
        ull uu[I_];
#pragma unroll
        for (int i = 0; i < I_; i++) uu[i] = pack2(ur[p][i], ur[p][i]);

        __half2* rec = g_uhat + ((size_t)(p0 + p) * B_ + t) * (C_ * 8);

#pragma unroll 1
        for (int c = 0; c < C_; c++) {
            const ulonglong2* w2 = (const ulonglong2*)(Ws + (p * C_ + c) * (I_ * O_));
            ull a[8];
#pragma unroll
            for (int k = 0; k < 8; k++) a[k] = 0ULL;
#pragma unroll
            for (int i = 0; i < I_; i++) {
                ulonglong2 q0 = w2[i * 4 + 0];
                ulonglong2 q1 = w2[i * 4 + 1];
                ulonglong2 q2 = w2[i * 4 + 2];
                ulonglong2 q3 = w2[i * 4 + 3];
                a[0] = ffma2(q0.x, uu[i], a[0]);
                a[1] = ffma2(q0.y, uu[i], a[1]);
                a[2] = ffma2(q1.x, uu[i], a[2]);
                a[3] = ffma2(q1.y, uu[i], a[3]);
                a[4] = ffma2(q2.x, uu[i], a[4]);
                a[5] = ffma2(q2.y, uu[i], a[5]);
                a[6] = ffma2(q3.x, uu[i], a[6]);
                a[7] = ffma2(q3.y, uu[i], a[7]);
            }
            union { __half2 h[8]; uint4 q[2]; } ou;
#pragma unroll
            for (int k = 0; k < 8; k++) {
                float2 f = unpack2(a[k]);
                ou.h[k] = __floats2half2_rn(f.x, f.y);
            }
            uint4* dst = (uint4*)(rec + c * 8);
            dst[0] = ou.q[0];
            dst[1] = ou.q[1];
        }
    }
}

// ---------------------------------------------------------------------------
// Routing pass, barrier-free. 16-lane group = one (b,p) record; lane = c
// (10 active, 6 idle). Softmax Z via 4-step shfl_xor butterfly in-group.
// Each active lane owns one c -> 16-float fp32 accumulator in regs.
// Partial s written per p-chunk block (no atomics).
// ---------------------------------------------------------------------------
template <bool UNIFORM>
__global__ void __launch_bounds__(256) k_route() {
    const int t = threadIdx.x;
    const int w = t >> 5;                 // warp 0..7
    const int h = (t >> 4) & 1;           // half-warp
    const int c16 = t & 15;               // lane within group = c
    const bool active = (c16 < C_);
    const int cc = active ? c16 : 0;      // clamped for safe addressing
    const int b = blockIdx.y * 16 + w * 2 + h;
    const int p0 = blockIdx.x * PCH;

    __half2 vsh[8];
    if (!UNIFORM) {
        const float4* vp = (const float4*)(g_vsum + (b * C_ + cc) * O_);
#pragma unroll
        for (int k = 0; k < 4; k++) {
            float4 v4 = vp[k];
            vsh[2 * k + 0] = __floats2half2_rn(v4.x, v4.y);
            vsh[2 * k + 1] = __floats2half2_rn(v4.z, v4.w);
        }
    }

    ull acc[8];
#pragma unroll
    for (int k = 0; k < 8; k++) acc[k] = 0ULL;

#pragma unroll 1
    for (int p = p0; p < p0 + PCH; p += 2) {
        union { uint4 q[2]; __half2 h2[8]; } uu[2];
        // Batched coalesced loads: group's 10 active lanes cover the full
        // 320B record; idle lanes re-read c=0 (harmless, L1 hit).
#pragma unroll
        for (int j = 0; j < 2; j++) {
            const uint4* src =
                (const uint4*)(g_uhat + ((size_t)(p + j) * B_ + b) * (C_ * 8) + cc * 8);
            uu[j].q[0] = src[0];
            uu[j].q[1] = src[1];
        }

        float cw[2];
        if (UNIFORM) {
            cw[0] = cw[1] = 0.1f;
        } else {
            float e[2];
#pragma unroll
            for (int j = 0; j < 2; j++) {
                __half2 lg = __floats2half2_rn(0.f, 0.f);
#pragma unroll
                for (int k = 0; k < 8; k++) lg = __hfma2(uu[j].h2[k], vsh[k], lg);
                float l = __low2float(lg) + __high2float(lg);
                e[j] = active ? __expf(l) : 0.f;   // |logit| small: no max-sub
            }
            float Z0 = e[0], Z1 = e[1];
#pragma unroll
            for (int d = 1; d < 16; d <<= 1) {
                Z0 += __shfl_xor_sync(0xffffffffu, Z0, d);
                Z1 += __shfl_xor_sync(0xffffffffu, Z1, d);
            }
            cw[0] = e[0] * rcp_fast(Z0);
            cw[1] = e[1] * rcp_fast(Z1);
        }

        if (active) {
#pragma unroll
            for (int j = 0; j < 2; j++) {
                ull cw2 = pack2(cw[j], cw[j]);
#pragma unroll
                for (int k = 0; k < 8; k++) {
                    float2 f = __half22float2(uu[j].h2[k]);
                    acc[k] = ffma2(cw2, pack2(f.x, f.y), acc[k]);
                }
            }
        }
    }

    if (active) {
        float4* dst = (float4*)(g_part + (size_t)blockIdx.x * SSZ + (b * C_ + c16) * O_);
#pragma unroll
        for (int k = 0; k < 4; k++) {
            float2 f0 = unpack2(acc[2 * k + 0]);
            float2 f1 = unpack2(acc[2 * k + 1]);
            dst[k] = make_float4(f0.x, f0.y, f1.x, f1.y);
        }
    }
}

// ---------------------------------------------------------------------------
// Squash: sum the 64 partials, then v = (|s|^2/(1+|s|^2)) * s/sqrt(|s|^2+eps).
// MODE 0: vsum = v.  MODE 1: vsum += v.  MODE 2: out = v.
// thread idx -> (b, c, o); o = idx&15 aligns with 16-lane shuffle groups.
// ---------------------------------------------------------------------------
template <int MODE>
__global__ void __launch_bounds__(640) k_squash(float* __restrict__ out) {
    const int idx = blockIdx.x * 640 + threadIdx.x;

    float sv = 0.f;
#pragma unroll 8
    for (int k = 0; k < NCHUNK; k++) sv += g_part[(size_t)k * SSZ + idx];

    float n2 = sv * sv;
#pragma unroll
    for (int d = 1; d < 16; d <<= 1) n2 += __shfl_xor_sync(0xffffffffu, n2, d);

    float scale = (n2 / (1.f + n2)) * rsqrtf(n2 + 1e-9f);
    float v = sv * scale;

    if (MODE == 0) {
        g_vsum[idx] = v;
    } else if (MODE == 1) {
        g_vsum[idx] += v;
    } else {
        out[idx] = v;
    }
}

// ---------------------------------------------------------------------------
extern "C" void kernel_launch(void* const* d_in, const int* in_sizes, int n_in,
                              void* d_out, int out_size) {
    const float* u = (const float*)d_in[0];
    const float* W = (const float*)d_in[1];
    if (n_in >= 2 && in_sizes[0] == P_ * C_ * O_ * I_ && in_sizes[1] == B_ * P_ * I_) {
        const float* tmp = u; u = W; W = tmp;
    }
    float* out = (float*)d_out;

    dim3 rg(NCHUNK, B_ / 16);  // (64, 16) = 1024 blocks

    k_uhat<<<P_ / PT, 256>>>(u, W);                // 1024 blocks

    k_route<true><<<rg, 256>>>();                  // iter 1 (uniform weights)
    k_squash<0><<<SSZ / 640, 640>>>(out);          // v1 -> vsum

    k_route<false><<<rg, 256>>>();                 // iter 2
    k_squash<1><<<SSZ / 640, 640>>>(out);          // vsum += v2

    k_route<false><<<rg, 256>>>();                 // iter 3
    k_squash<2><<<SSZ / 640, 640>>>(out);          // out = v3
}

// round 5
// speedup vs baseline: 1.6697x; 1.0903x over previous
#include <cuda_runtime.h>
#include <cuda_fp16.h>

#define B_ 256
#define P_ 2048
#define C_ 10
#define O_ 16
#define I_ 8
#define PCH 32               // p's per routing block
#define NCHUNK (P_ / PCH)    // 64 routing p-chunks
#define SSZ (B_ * C_ * O_)   // 40960
#define RSTRIDE 336          // padded record stride in stage smem (bytes)
#define JJ 4                 // p-unroll in routing

// u_hat fp16, layout [p][b][c][o2]: one (b,p) record = 320B contiguous.
__device__ __align__(16) __half2 g_uhat[(size_t)P_ * B_ * C_ * (O_ / 2)];
// Per-p-chunk partial s sums (plain stores, no atomics): [chunk][b][c][o].
__device__ __align__(16) float g_part[NCHUNK * SSZ];
__device__ __align__(16) float g_vsum[SSZ];

typedef unsigned long long ull;

__device__ __forceinline__ ull ffma2(ull a, ull b, ull c) {
    ull d;
    asm("fma.rn.f32x2 %0, %1, %2, %3;" : "=l"(d) : "l"(a), "l"(b), "l"(c));
    return d;
}
__device__ __forceinline__ ull pack2(float x, float y) {
    ull r;
    asm("mov.b64 %0, {%1, %2};" : "=l"(r) : "f"(x), "f"(y));
    return r;
}
__device__ __forceinline__ float2 unpack2(ull a) {
    float2 f;
    asm("mov.b64 {%0, %1}, %2;" : "=f"(f.x), "=f"(f.y) : "l"(a));
    return f;
}
__device__ __forceinline__ float rcp_fast(float x) {
    float r;
    asm("rcp.approx.f32 %0, %1;" : "=f"(r) : "f"(x));
    return r;
}
__device__ __forceinline__ float ex2_fast(float x) {
    float r;
    asm("ex2.approx.f32 %0, %1;" : "=f"(r) : "f"(x));
    return r;
}

// ---------------------------------------------------------------------------
// K1: u_hat[p][b][c][o] = sum_i W[p,c,o,i]*u[b,p,i], fp16 out.
// One p per block, 256 threads (= b). Compute into padded smem stage
// (conflict-free STS), then flush the whole 80KB p-slab with fully
// coalesced 16B stores (kills the 32-wavefront strided-store problem).
// ---------------------------------------------------------------------------
__global__ void __launch_bounds__(256) k_uhat(const float* __restrict__ u,
                                              const float* __restrict__ W) {
    extern __shared__ char sm[];
    float* Ws = (float*)sm;                    // [c][i][o], 1280 floats
    char* stage = sm + C_ * I_ * O_ * 4;       // 256 records * RSTRIDE

    const int t = threadIdx.x;                 // = b
    const int p = blockIdx.x;

    // Load + transpose W[p] ([c][o][i] -> [c][i][o]); 320 float4s, 256 thr.
    {
        const float4* Wg = (const float4*)(W + (size_t)p * C_ * O_ * I_);
#pragma unroll
        for (int k = 0; k < 2; k++) {
            int idx = t + k * 256;
            if (idx < (C_ * O_ * I_) / 4) {
                float4 w4 = Wg[idx];
                int L = idx * 4;
                int i = L & 7;                 // 0 or 4
                int o = (L >> 3) & 15;
                int c = L >> 7;
                float* dst = Ws + c * (I_ * O_) + o;
                dst[(i + 0) * O_] = w4.x;
                dst[(i + 1) * O_] = w4.y;
                dst[(i + 2) * O_] = w4.z;
                dst[(i + 3) * O_] = w4.w;
            }
        }
    }

    // u[b, p, :] (32B per thread).
    ull uu[I_];
    {
        const float4* ug = (const float4*)(u + ((size_t)t * P_ + p) * I_);
        float4 a = ug[0];
        float4 d = ug[1];
        uu[0] = pack2(a.x, a.x); uu[1] = pack2(a.y, a.y);
        uu[2] = pack2(a.z, a.z); uu[3] = pack2(a.w, a.w);
        uu[4] = pack2(d.x, d.x); uu[5] = pack2(d.y, d.y);
        uu[6] = pack2(d.z, d.z); uu[7] = pack2(d.w, d.w);
    }
    __syncthreads();

#pragma unroll 1
    for (int c = 0; c < C_; c++) {
        const ulonglong2* w2 = (const ulonglong2*)(Ws + c * (I_ * O_));
        ull a[8];
#pragma unroll
        for (int k = 0; k < 8; k++) a[k] = 0ULL;
#pragma unroll
        for (int i = 0; i < I_; i++) {
            ulonglong2 q0 = w2[i * 4 + 0];
            ulonglong2 q1 = w2[i * 4 + 1];
            ulonglong2 q2 = w2[i * 4 + 2];
            ulonglong2 q3 = w2[i * 4 + 3];
            a[0] = ffma2(q0.x, uu[i], a[0]);
            a[1] = ffma2(q0.y, uu[i], a[1]);
            a[2] = ffma2(q1.x, uu[i], a[2]);
            a[3] = ffma2(q1.y, uu[i], a[3]);
            a[4] = ffma2(q2.x, uu[i], a[4]);
            a[5] = ffma2(q2.y, uu[i], a[5]);
            a[6] = ffma2(q3.x, uu[i], a[6]);
            a[7] = ffma2(q3.y, uu[i], a[7]);
        }
        union { __half2 h[8]; uint4 q[2]; } ou;
#pragma unroll
        for (int k = 0; k < 8; k++) {
            float2 f = unpack2(a[k]);
            ou.h[k] = __floats2half2_rn(f.x, f.y);
        }
        uint4* dst = (uint4*)(stage + t * RSTRIDE + c * 32);
        dst[0] = ou.q[0];
        dst[1] = ou.q[1];
    }
    __syncthreads();

    // Flush: 5120 uint4 (80KB) -> global, fully coalesced (4KB per pass).
    uint4* out4 = (uint4*)g_uhat + (size_t)p * (B_ * 20);
#pragma unroll
    for (int k = 0; k < 20; k++) {
        int g = t + k * 256;
        int b = g / 20;
        int j = g - b * 20;
        out4[g] = *(const uint4*)(stage + b * RSTRIDE + j * 16);
    }
}

// ---------------------------------------------------------------------------
// Routing pass, barrier-free. 16-lane group = one (b,p) record; lane = c
// (10 active, 6 idle). Softmax Z via shfl_xor butterfly in-group; exp done
// as ex2 with log2e pre-folded into vsum. JJ=4 p's batched for MLP.
// Partial s written per p-chunk block (no atomics).
// ---------------------------------------------------------------------------
template <bool UNIFORM>
__global__ void __launch_bounds__(256) k_route() {
    const int t = threadIdx.x;
    const int w = t >> 5;                 // warp 0..7
    const int h = (t >> 4) & 1;           // half-warp
    const int c16 = t & 15;               // lane within group = c
    const bool active = (c16 < C_);
    const int cc = active ? c16 : 0;      // clamped for safe addressing
    const int b = blockIdx.y * 16 + w * 2 + h;
    const int p0 = blockIdx.x * PCH;

    __half2 vsh[8];
    if (!UNIFORM) {
        const float4* vp = (const float4*)(g_vsum + (b * C_ + cc) * O_);
        const float L2E = 1.4426950408889634f;
#pragma unroll
        for (int k = 0; k < 4; k++) {
            float4 v4 = vp[k];
            vsh[2 * k + 0] = __floats2half2_rn(v4.x * L2E, v4.y * L2E);
            vsh[2 * k + 1] = __floats2half2_rn(v4.z * L2E, v4.w * L2E);
        }
    }

    ull acc[8];
#pragma unroll
    for (int k = 0; k < 8; k++) acc[k] = 0ULL;

#pragma unroll 1
    for (int p = p0; p < p0 + PCH; p += JJ) {
        union { uint4 q[2]; __half2 h2[8]; } uu[JJ];
        // Batched coalesced loads: the group's 10 active lanes cover the
        // full 320B record; idle lanes re-read c=0 (same sectors, L1 hit).
#pragma unroll
        for (int j = 0; j < JJ; j++) {
            const uint4* src =
                (const uint4*)(g_uhat + ((size_t)(p + j) * B_ + b) * (C_ * 8) + cc * 8);
            uu[j].q[0] = src[0];
            uu[j].q[1] = src[1];
        }

        float cw[JJ];
        if (UNIFORM) {
#pragma unroll
            for (int j = 0; j < JJ; j++) cw[j] = 0.1f;
        } else {
            float e[JJ];
#pragma unroll
            for (int j = 0; j < JJ; j++) {
                __half2 lg = __floats2half2_rn(0.f, 0.f);
#pragma unroll
                for (int k = 0; k < 8; k++) lg = __hfma2(uu[j].h2[k], vsh[k], lg);
                float l = __low2float(lg) + __high2float(lg);
                e[j] = active ? ex2_fast(l) : 0.f;   // logit pre-scaled by log2e
            }
            float Z[JJ];
#pragma unroll
            for (int j = 0; j < JJ; j++) Z[j] = e[j];
#pragma unroll
            for (int d = 1; d < 16; d <<= 1)
#pragma unroll
                for (int j = 0; j < JJ; j++)
                    Z[j] += __shfl_xor_sync(0xffffffffu, Z[j], d);
#pragma unroll
            for (int j = 0; j < JJ; j++) cw[j] = e[j] * rcp_fast(Z[j]);
        }

        if (active) {
#pragma unroll
            for (int j = 0; j < JJ; j++) {
                ull cw2 = pack2(cw[j], cw[j]);
#pragma unroll
                for (int k = 0; k < 8; k++) {
                    float2 f = __half22float2(uu[j].h2[k]);
                    acc[k] = ffma2(cw2, pack2(f.x, f.y), acc[k]);
                }
            }
        }
    }

    if (active) {
        float4* dst = (float4*)(g_part + (size_t)blockIdx.x * SSZ + (b * C_ + c16) * O_);
#pragma unroll
        for (int k = 0; k < 4; k++) {
            float2 f0 = unpack2(acc[2 * k + 0]);
            float2 f1 = unpack2(acc[2 * k + 1]);
            dst[k] = make_float4(f0.x, f0.y, f1.x, f1.y);
        }
    }
}

// ---------------------------------------------------------------------------
// Squash: sum the 64 partials, then v = (|s|^2/(1+|s|^2)) * s/sqrt(|s|^2+eps).
// MODE 0: vsum = v.  MODE 1: vsum += v.  MODE 2: out = v.
// ---------------------------------------------------------------------------
template <int MODE>
__global__ void __launch_bounds__(640) k_squash(float* __restrict__ out) {
    const int idx = blockIdx.x * 640 + threadIdx.x;

    float sv = 0.f;
#pragma unroll 8
    for (int k = 0; k < NCHUNK; k++) sv += g_part[(size_t)k * SSZ + idx];

    float n2 = sv * sv;
#pragma unroll
    for (int d = 1; d < 16; d <<= 1) n2 += __shfl_xor_sync(0xffffffffu, n2, d);

    float scale = (n2 / (1.f + n2)) * rsqrtf(n2 + 1e-9f);
    float v = sv * scale;

    if (MODE == 0) {
        g_vsum[idx] = v;
    } else if (MODE == 1) {
        g_vsum[idx] += v;
    } else {
        out[idx] = v;
    }
}

// ---------------------------------------------------------------------------
extern "C" void kernel_launch(void* const* d_in, const int* in_sizes, int n_in,
                              void* d_out, int out_size) {
    const float* u = (const float*)d_in[0];
    const float* W = (const float*)d_in[1];
    if (n_in >= 2 && in_sizes[0] == P_ * C_ * O_ * I_ && in_sizes[1] == B_ * P_ * I_) {
        const float* tmp = u; u = W; W = tmp;
    }
    float* out = (float*)d_out;

    const int uhat_smem = C_ * I_ * O_ * 4 + B_ * RSTRIDE;  // 5120 + 86016
    static int attr_set = 0;
    if (!attr_set) {
        cudaFuncSetAttribute(k_uhat, cudaFuncAttributeMaxDynamicSharedMemorySize,
                             uhat_smem);
        attr_set = 1;
    }

    dim3 rg(NCHUNK, B_ / 16);  // (64, 16) = 1024 blocks

    k_uhat<<<P_, 256, uhat_smem>>>(u, W);          // 2048 blocks

    k_route<true><<<rg, 256>>>();                  // iter 1 (uniform weights)
    k_squash<0><<<SSZ / 640, 640>>>(out);          // v1 -> vsum

    k_route<false><<<rg, 256>>>();                 // iter 2
    k_squash<1><<<SSZ / 640, 640>>>(out);          // vsum += v2

    k_route<false><<<rg, 256>>>();                 // iter 3
    k_squash<2><<<SSZ / 640, 640>>>(out);          // out = v3
}